// round 3
// baseline (speedup 1.0000x reference)
#include <cuda_runtime.h>
#include <cuda_bf16.h>
#include <cstdint>

// Problem constants
// x:      [4, 1024, 1024]  fp32
// W_qkv:  [1024, 3072]     fp32   (columns: K | Q | V, 1024 each; per-third layout [H=16, hd=64])
// b_qkv:  [3072]
// W_out:  [1024, 1024]
// b_out:  [1024]
// out:    [4, 1024, 1024]
static constexpr int B_   = 4;
static constexpr int N_   = 1024;
static constexpr int EMB  = 1024;
static constexpr int H_   = 16;
static constexpr int HD   = 64;
static constexpr int QKV  = 3 * H_ * HD;   // 3072
static constexpr int M_   = B_ * N_;       // 4096

// Scratch (no allocation allowed -> device globals)
__device__ float g_qkv[M_ * QKV];      // 48 MB
__device__ float g_att[M_ * EMB];      // 16 MB

// ---------------------------------------------------------------------------
// SGEMM with bias: C[M,N] = A[M,K] @ B[K,N] + bias[N]
// 128x128 CTA tile, BK=8, 256 threads, 8x8 per-thread register tile.
// ---------------------------------------------------------------------------
__global__ __launch_bounds__(256, 2)
void sgemm_bias_kernel(const float* __restrict__ A,
                       const float* __restrict__ Bm,
                       const float* __restrict__ bias,
                       float* __restrict__ C,
                       int M, int N, int K)
{
    __shared__ float As[8][128];   // transposed A tile: As[k][m]
    __shared__ float Bs[8][128];   // Bs[k][n]

    const int tid = threadIdx.x;
    const int ty  = tid >> 4;          // 0..15
    const int tx  = tid & 15;          // 0..15
    const int rowBase = blockIdx.y * 128;
    const int colBase = blockIdx.x * 128;

    // gmem load mapping
    const int arow = tid >> 1;         // 0..127
    const int acol = (tid & 1) * 4;    // 0 or 4
    const int brow = tid >> 5;         // 0..7
    const int bcol = (tid & 31) * 4;   // 0..124

    float acc[8][8];
    #pragma unroll
    for (int i = 0; i < 8; i++)
        #pragma unroll
        for (int j = 0; j < 8; j++) acc[i][j] = 0.0f;

    for (int kt = 0; kt < K; kt += 8) {
        const float4 a4 = *reinterpret_cast<const float4*>(
            &A[(size_t)(rowBase + arow) * K + kt + acol]);
        const float4 b4 = *reinterpret_cast<const float4*>(
            &Bm[(size_t)(kt + brow) * N + colBase + bcol]);

        __syncthreads();   // previous compute done reading smem
        As[acol + 0][arow] = a4.x;
        As[acol + 1][arow] = a4.y;
        As[acol + 2][arow] = a4.z;
        As[acol + 3][arow] = a4.w;
        *reinterpret_cast<float4*>(&Bs[brow][bcol]) = b4;
        __syncthreads();

        #pragma unroll
        for (int k = 0; k < 8; k++) {
            float a[8], b[8];
            float4 a0 = *reinterpret_cast<const float4*>(&As[k][ty * 8]);
            float4 a1 = *reinterpret_cast<const float4*>(&As[k][ty * 8 + 4]);
            float4 b0 = *reinterpret_cast<const float4*>(&Bs[k][tx * 8]);
            float4 b1 = *reinterpret_cast<const float4*>(&Bs[k][tx * 8 + 4]);
            a[0]=a0.x; a[1]=a0.y; a[2]=a0.z; a[3]=a0.w;
            a[4]=a1.x; a[5]=a1.y; a[6]=a1.z; a[7]=a1.w;
            b[0]=b0.x; b[1]=b0.y; b[2]=b0.z; b[3]=b0.w;
            b[4]=b1.x; b[5]=b1.y; b[6]=b1.z; b[7]=b1.w;
            #pragma unroll
            for (int i = 0; i < 8; i++)
                #pragma unroll
                for (int j = 0; j < 8; j++)
                    acc[i][j] = fmaf(a[i], b[j], acc[i][j]);
        }
    }

    // epilogue with bias
    #pragma unroll
    for (int i = 0; i < 8; i++) {
        const int row = rowBase + ty * 8 + i;
        const int col = colBase + tx * 8;
        float4 bi0 = *reinterpret_cast<const float4*>(&bias[col]);
        float4 bi1 = *reinterpret_cast<const float4*>(&bias[col + 4]);
        float4 c0 = make_float4(acc[i][0] + bi0.x, acc[i][1] + bi0.y,
                                acc[i][2] + bi0.z, acc[i][3] + bi0.w);
        float4 c1 = make_float4(acc[i][4] + bi1.x, acc[i][5] + bi1.y,
                                acc[i][6] + bi1.z, acc[i][7] + bi1.w);
        *reinterpret_cast<float4*>(&C[(size_t)row * N + col])     = c0;
        *reinterpret_cast<float4*>(&C[(size_t)row * N + col + 4]) = c1;
    }
}

// ---------------------------------------------------------------------------
// Flash attention over one (b, h, 64-row q tile).
// grid = (16 qtiles, 64 bh), block = 256 threads (16x16), 4x4 per-thread tile.
// qkv columns: [0:1024)=K, [1024:2048)=Q, [2048:3072)=V (torch.split K,Q,V).
// ---------------------------------------------------------------------------
static constexpr int FA_SMEM =
    (64 * 64 + 64 * 65 + 64 * 64 + 64 * 64) * (int)sizeof(float);  // 65792 B

__global__ __launch_bounds__(256, 2)
void flash_attn_kernel(const float* __restrict__ qkv, float* __restrict__ attout)
{
    extern __shared__ float smem[];
    float* Qs  = smem;                 // [64][64]  (scaled by 1/8)
    float* KsT = Qs  + 64 * 64;        // [64][65]  K transposed, pitch 65
    float* Vs  = KsT + 64 * 65;        // [64][64]
    float* Ps  = Vs  + 64 * 64;        // [64][64]

    const int tid = threadIdx.x;
    const int ty  = tid >> 4;          // 0..15 -> rows ty*4..ty*4+3
    const int tx  = tid & 15;          // 0..15 -> cols tx*4..tx*4+3
    const int qtile = blockIdx.x;      // 0..15
    const int bh    = blockIdx.y;      // 0..63
    const int b = bh >> 4, h = bh & 15;

    const size_t base = (size_t)b * N_ * QKV;
    const int hcol = h * HD;
    const float scale = 0.125f;        // 1/sqrt(64)

    // load Q tile (rows qtile*64 .. +63), pre-scaled
    #pragma unroll
    for (int i = 0; i < 16; i++) {
        const int e = tid + i * 256;
        const int r = e >> 6, d = e & 63;
        Qs[r * 64 + d] = qkv[base + (size_t)(qtile * 64 + r) * QKV + 1024 + hcol + d] * scale;
    }

    float o[4][4], m[4], l[4];
    #pragma unroll
    for (int i = 0; i < 4; i++) {
        m[i] = -1e30f; l[i] = 0.0f;
        #pragma unroll
        for (int j = 0; j < 4; j++) o[i][j] = 0.0f;
    }

    for (int kt = 0; kt < 16; kt++) {
        __syncthreads();  // prior PV done reading Vs/Ps; Q visible after first pass
        // load K tile -> KsT[d][n], V tile -> Vs[n][d]
        #pragma unroll
        for (int i = 0; i < 16; i++) {
            const int e = tid + i * 256;
            const int r = e >> 6, d = e & 63;
            const size_t rowoff = base + (size_t)(kt * 64 + r) * QKV + hcol + d;
            KsT[d * 65 + r] = qkv[rowoff];          // K third (offset 0)
            Vs [r * 64 + d] = qkv[rowoff + 2048];   // V third
        }
        __syncthreads();

        // S = Qs @ K^T  (4x4 per thread)
        float s[4][4];
        #pragma unroll
        for (int i = 0; i < 4; i++)
            #pragma unroll
            for (int j = 0; j < 4; j++) s[i][j] = 0.0f;

        #pragma unroll 8
        for (int k = 0; k < 64; k++) {
            float a[4], bb[4];
            #pragma unroll
            for (int i = 0; i < 4; i++) a[i]  = Qs[(ty * 4 + i) * 64 + k];
            #pragma unroll
            for (int j = 0; j < 4; j++) bb[j] = KsT[k * 65 + tx * 4 + j];
            #pragma unroll
            for (int i = 0; i < 4; i++)
                #pragma unroll
                for (int j = 0; j < 4; j++)
                    s[i][j] = fmaf(a[i], bb[j], s[i][j]);
        }

        // online softmax update (row groups = 16 lanes sharing ty)
        #pragma unroll
        for (int i = 0; i < 4; i++) {
            float tmax = fmaxf(fmaxf(s[i][0], s[i][1]), fmaxf(s[i][2], s[i][3]));
            #pragma unroll
            for (int off = 8; off >= 1; off >>= 1)
                tmax = fmaxf(tmax, __shfl_xor_sync(0xffffffffu, tmax, off, 32));
            const float mnew = fmaxf(m[i], tmax);
            const float corr = __expf(m[i] - mnew);
            m[i] = mnew;
            float tsum = 0.0f;
            #pragma unroll
            for (int j = 0; j < 4; j++) {
                s[i][j] = __expf(s[i][j] - mnew);
                tsum += s[i][j];
            }
            #pragma unroll
            for (int off = 8; off >= 1; off >>= 1)
                tsum += __shfl_xor_sync(0xffffffffu, tsum, off, 32);
            l[i] = l[i] * corr + tsum;
            #pragma unroll
            for (int j = 0; j < 4; j++) o[i][j] *= corr;
        }

        // write P (Ps is disjoint from KsT so no extra sync needed before write)
        #pragma unroll
        for (int i = 0; i < 4; i++) {
            float4 v = make_float4(s[i][0], s[i][1], s[i][2], s[i][3]);
            *reinterpret_cast<float4*>(&Ps[(ty * 4 + i) * 64 + tx * 4]) = v;
        }
        __syncthreads();

        // O += P @ V
        #pragma unroll 8
        for (int kk = 0; kk < 64; kk++) {
            float p[4];
            #pragma unroll
            for (int i = 0; i < 4; i++) p[i] = Ps[(ty * 4 + i) * 64 + kk];
            const float4 vv = *reinterpret_cast<const float4*>(&Vs[kk * 64 + tx * 4]);
            const float vb[4] = { vv.x, vv.y, vv.z, vv.w };
            #pragma unroll
            for (int i = 0; i < 4; i++)
                #pragma unroll
                for (int j = 0; j < 4; j++)
                    o[i][j] = fmaf(p[i], vb[j], o[i][j]);
        }
    }

    // epilogue: att[(b*1024 + n), h*64 + d] = o / l   (heads re-interleaved)
    #pragma unroll
    for (int i = 0; i < 4; i++) {
        const float inv = 1.0f / l[i];
        const int n = qtile * 64 + ty * 4 + i;
        float4 v = make_float4(o[i][0] * inv, o[i][1] * inv,
                               o[i][2] * inv, o[i][3] * inv);
        *reinterpret_cast<float4*>(
            &attout[((size_t)b * N_ + n) * EMB + hcol + tx * 4]) = v;
    }
}

// ---------------------------------------------------------------------------
extern "C" void kernel_launch(void* const* d_in, const int* in_sizes, int n_in,
                              void* d_out, int out_size)
{
    const float* x     = (const float*)d_in[0];
    const float* W_qkv = (const float*)d_in[1];
    const float* b_qkv = (const float*)d_in[2];
    const float* W_out = (const float*)d_in[3];
    const float* b_out = (const float*)d_in[4];
    float* out = (float*)d_out;

    float *qkvbuf = nullptr, *attbuf = nullptr;
    cudaGetSymbolAddress((void**)&qkvbuf, g_qkv);
    cudaGetSymbolAddress((void**)&attbuf, g_att);

    cudaFuncSetAttribute(flash_attn_kernel,
                         cudaFuncAttributeMaxDynamicSharedMemorySize, FA_SMEM);

    // 1) QKV projection: [4096,1024] @ [1024,3072] + b_qkv
    sgemm_bias_kernel<<<dim3(QKV / 128, M_ / 128), 256>>>(
        x, W_qkv, b_qkv, qkvbuf, M_, QKV, EMB);

    // 2) attention: 16 q-tiles x 64 (b,h) pairs
    flash_attn_kernel<<<dim3(16, B_ * H_), 256, FA_SMEM>>>(qkvbuf, attbuf);

    // 3) output projection: [4096,1024] @ [1024,1024] + b_out
    sgemm_bias_kernel<<<dim3(EMB / 128, M_ / 128), 256>>>(
        attbuf, W_out, b_out, out, M_, EMB, EMB);
}

// round 10
// speedup vs baseline: 1.3240x; 1.3240x over previous
#include <cuda_runtime.h>
#include <cuda_bf16.h>
#include <cstdint>

// Problem constants
static constexpr int B_   = 4;
static constexpr int N_   = 1024;
static constexpr int EMB  = 1024;
static constexpr int H_   = 16;
static constexpr int HD   = 64;
static constexpr int QKV  = 3 * H_ * HD;   // 3072
static constexpr int M_   = B_ * N_;       // 4096

// ---------------------------------------------------------------------------
// Scratch (device globals; no runtime allocation allowed)
// ---------------------------------------------------------------------------
__device__ float g_qkv[M_ * QKV];                 // 48 MB  (fp32 qkv)
__device__ float g_att[M_ * EMB];                 // 16 MB  (fp32 attention out)
__device__ __nv_bfloat16 g_xh[M_ * EMB];          // 8 MB
__device__ __nv_bfloat16 g_xl[M_ * EMB];          // 8 MB
__device__ __nv_bfloat16 g_WqTh[QKV * EMB];       // 6 MB (W_qkv^T hi)
__device__ __nv_bfloat16 g_WqTl[QKV * EMB];       // 6 MB
__device__ __nv_bfloat16 g_WoTh[EMB * EMB];       // 2 MB (W_out^T hi)
__device__ __nv_bfloat16 g_WoTl[EMB * EMB];       // 2 MB
__device__ __nv_bfloat16 g_ath[M_ * EMB];         // 8 MB
__device__ __nv_bfloat16 g_atl[M_ * EMB];         // 8 MB

// Dynamic smem only used by flash attention (float-typed view of bytes).
extern __shared__ __align__(1024) uint8_t dynsmem[];

// ---------------------------------------------------------------------------
// Helpers
// ---------------------------------------------------------------------------
__device__ __forceinline__ uint32_t smem_to_u32(const void* smem_ptr) {
    uint32_t addr;
    asm("{ .reg .u64 tmp; cvta.to.shared.u64 tmp, %1; cvt.u32.u64 %0, tmp; }"
        : "=r"(addr) : "l"(smem_ptr));
    return addr;
}

#define CP_ASYNC_16(smem_u32, gptr) \
    asm volatile("cp.async.cg.shared.global [%0], [%1], 16;" \
                 :: "r"(smem_u32), "l"(gptr) : "memory")
#define CP_ASYNC_COMMIT() asm volatile("cp.async.commit_group;" ::: "memory")
#define CP_ASYNC_WAIT0()  asm volatile("cp.async.wait_group 0;" ::: "memory")

__device__ __forceinline__ void mma16816(float& c0, float& c1, float& c2, float& c3,
                                         uint32_t a0, uint32_t a1, uint32_t a2, uint32_t a3,
                                         uint32_t b0, uint32_t b1) {
    asm volatile(
        "mma.sync.aligned.m16n8k16.row.col.f32.bf16.bf16.f32 "
        "{%0,%1,%2,%3}, {%4,%5,%6,%7}, {%8,%9}, {%0,%1,%2,%3};"
        : "+f"(c0), "+f"(c1), "+f"(c2), "+f"(c3)
        : "r"(a0), "r"(a1), "r"(a2), "r"(a3), "r"(b0), "r"(b1));
}

// ---------------------------------------------------------------------------
// Elementwise fp32 -> (bf16 hi, bf16 lo) split
// ---------------------------------------------------------------------------
__global__ void split_kernel(const float* __restrict__ in,
                             __nv_bfloat16* __restrict__ hi,
                             __nv_bfloat16* __restrict__ lo, int n4)
{
    const int i = blockIdx.x * blockDim.x + threadIdx.x;
    if (i >= n4) return;
    const float4 v = reinterpret_cast<const float4*>(in)[i];
    __nv_bfloat16 h0 = __float2bfloat16(v.x);
    __nv_bfloat16 h1 = __float2bfloat16(v.y);
    __nv_bfloat16 h2 = __float2bfloat16(v.z);
    __nv_bfloat16 h3 = __float2bfloat16(v.w);
    __nv_bfloat16 l0 = __float2bfloat16(v.x - __bfloat162float(h0));
    __nv_bfloat16 l1 = __float2bfloat16(v.y - __bfloat162float(h1));
    __nv_bfloat16 l2 = __float2bfloat16(v.z - __bfloat162float(h2));
    __nv_bfloat16 l3 = __float2bfloat16(v.w - __bfloat162float(h3));
    __nv_bfloat162* H = reinterpret_cast<__nv_bfloat162*>(hi);
    __nv_bfloat162* L = reinterpret_cast<__nv_bfloat162*>(lo);
    H[2*i]   = __nv_bfloat162(h0, h1);
    H[2*i+1] = __nv_bfloat162(h2, h3);
    L[2*i]   = __nv_bfloat162(l0, l1);
    L[2*i+1] = __nv_bfloat162(l2, l3);
}

// ---------------------------------------------------------------------------
// W [Kdim][Ndim] fp32 -> transposed split bf16 Th/Tl [Ndim][Kdim]
// ---------------------------------------------------------------------------
__global__ void transpose_split(const float* __restrict__ W,
                                __nv_bfloat16* __restrict__ Th,
                                __nv_bfloat16* __restrict__ Tl,
                                int Kdim, int Ndim)
{
    __shared__ float t[32][33];
    const int nb = blockIdx.x * 32;
    const int kb = blockIdx.y * 32;
    const int tx = threadIdx.x;
    const int ty = threadIdx.y;   // 0..7
    #pragma unroll
    for (int i = 0; i < 32; i += 8)
        t[ty + i][tx] = W[(size_t)(kb + ty + i) * Ndim + nb + tx];
    __syncthreads();
    #pragma unroll
    for (int i = 0; i < 32; i += 8) {
        const float v = t[tx][ty + i];
        const __nv_bfloat16 h = __float2bfloat16(v);
        const __nv_bfloat16 l = __float2bfloat16(v - __bfloat162float(h));
        const size_t o = (size_t)(nb + ty + i) * Kdim + kb + tx;
        Th[o] = h;
        Tl[o] = l;
    }
}

// ---------------------------------------------------------------------------
// HMMA (mma.sync bf16) split GEMM: C[M,N] = (Ah+Al)[M,1024] @ (Bh+Bl)^T + bias
//   A row-major [M][1024] bf16 hi/lo; B^T [N][1024] bf16 hi/lo.
//   3 K-passes accumulated in fp32 registers: Ah*Bh, Al*Bh, Ah*Bl.
//   CTA 128x128, BK=32, 256 threads, 8 warps @ 64x32, cp.async double buffer.
// ---------------------------------------------------------------------------
static constexpr int GPITCH = 40;  // bf16 per smem row (32 data + 8 pad) -> 80B

__global__ __launch_bounds__(256, 2)
void gemm_hmma_split(const __nv_bfloat16* __restrict__ Ah,
                     const __nv_bfloat16* __restrict__ Al,
                     const __nv_bfloat16* __restrict__ Bh,
                     const __nv_bfloat16* __restrict__ Bl,
                     const float* __restrict__ bias,
                     float* __restrict__ C, int N)
{
    __shared__ __align__(16) __nv_bfloat16 sA[2][128][GPITCH];
    __shared__ __align__(16) __nv_bfloat16 sB[2][128][GPITCH];

    const int tid  = threadIdx.x;
    const int wid  = tid >> 5;
    const int lane = tid & 31;
    const int wm   = wid & 1;          // 0..1  -> rows wm*64
    const int wn   = wid >> 1;         // 0..3  -> cols wn*32
    const int rowBase = blockIdx.y * 128;
    const int colBase = blockIdx.x * 128;
    constexpr int K = 1024;

    // gmem->smem mapping: each thread copies 2 x 16B for A and 2 x 16B for B.
    const int ldRow = tid >> 1;          // 0..127
    const int ldSeg = (tid & 1) * 2;     // 0 or 2 (16B segments of 8 bf16)

    const int lr = lane >> 2;            // 0..7
    const int lk = (lane & 3) * 2;       // 0,2,4,6

    float acc[4][4][4];
    #pragma unroll
    for (int mt = 0; mt < 4; mt++)
        #pragma unroll
        for (int nt = 0; nt < 4; nt++)
            #pragma unroll
            for (int q = 0; q < 4; q++) acc[mt][nt][q] = 0.0f;

    auto issue_loads = [&](int c, int buf) {
        const int p  = c >> 5;               // pass 0,1,2
        const int ks = (c & 31) * 32;        // K element offset
        const __nv_bfloat16* Ap = (p == 1) ? Al : Ah;
        const __nv_bfloat16* Bp = (p == 2) ? Bl : Bh;
        const __nv_bfloat16* ga = Ap + (size_t)(rowBase + ldRow) * K + ks + ldSeg * 8;
        const __nv_bfloat16* gb = Bp + (size_t)(colBase + ldRow) * K + ks + ldSeg * 8;
        const uint32_t saddr = smem_to_u32(&sA[buf][ldRow][ldSeg * 8]);
        const uint32_t sbddr = smem_to_u32(&sB[buf][ldRow][ldSeg * 8]);
        CP_ASYNC_16(saddr,      ga);
        CP_ASYNC_16(saddr + 16, ga + 8);
        CP_ASYNC_16(sbddr,      gb);
        CP_ASYNC_16(sbddr + 16, gb + 8);
        CP_ASYNC_COMMIT();
    };

    issue_loads(0, 0);

    for (int c = 0; c < 96; c++) {
        const int buf = c & 1;
        CP_ASYNC_WAIT0();
        __syncthreads();
        if (c + 1 < 96) issue_loads(c + 1, buf ^ 1);

        #pragma unroll
        for (int kk = 0; kk < 32; kk += 16) {
            // A fragments: 4 m-tiles of 16 rows
            uint32_t af[4][4];
            #pragma unroll
            for (int mt = 0; mt < 4; mt++) {
                const int r0 = wm * 64 + mt * 16 + lr;
                af[mt][0] = *reinterpret_cast<const uint32_t*>(&sA[buf][r0][kk + lk]);
                af[mt][1] = *reinterpret_cast<const uint32_t*>(&sA[buf][r0 + 8][kk + lk]);
                af[mt][2] = *reinterpret_cast<const uint32_t*>(&sA[buf][r0][kk + 8 + lk]);
                af[mt][3] = *reinterpret_cast<const uint32_t*>(&sA[buf][r0 + 8][kk + 8 + lk]);
            }
            // B fragments: 4 n-tiles of 8 cols
            uint32_t bf[4][2];
            #pragma unroll
            for (int nt = 0; nt < 4; nt++) {
                const int n0 = wn * 32 + nt * 8 + lr;
                bf[nt][0] = *reinterpret_cast<const uint32_t*>(&sB[buf][n0][kk + lk]);
                bf[nt][1] = *reinterpret_cast<const uint32_t*>(&sB[buf][n0][kk + 8 + lk]);
            }
            #pragma unroll
            for (int mt = 0; mt < 4; mt++)
                #pragma unroll
                for (int nt = 0; nt < 4; nt++)
                    mma16816(acc[mt][nt][0], acc[mt][nt][1],
                             acc[mt][nt][2], acc[mt][nt][3],
                             af[mt][0], af[mt][1], af[mt][2], af[mt][3],
                             bf[nt][0], bf[nt][1]);
        }
        __syncthreads();
    }

    // Epilogue with bias (C fragment: c0,c1 @ {row=lane/4, col=2*(lane%4)}, c2,c3 row+8)
    #pragma unroll
    for (int mt = 0; mt < 4; mt++) {
        const int r0 = rowBase + wm * 64 + mt * 16 + (lane >> 2);
        #pragma unroll
        for (int nt = 0; nt < 4; nt++) {
            const int col = colBase + wn * 32 + nt * 8 + (lane & 3) * 2;
            const float b0 = bias[col], b1 = bias[col + 1];
            float2 v0 = make_float2(acc[mt][nt][0] + b0, acc[mt][nt][1] + b1);
            float2 v1 = make_float2(acc[mt][nt][2] + b0, acc[mt][nt][3] + b1);
            *reinterpret_cast<float2*>(&C[(size_t)r0 * N + col])       = v0;
            *reinterpret_cast<float2*>(&C[(size_t)(r0 + 8) * N + col]) = v1;
        }
    }
}

// ---------------------------------------------------------------------------
// Flash attention over one (b, h, 64-row q tile)  (fp32)
// ---------------------------------------------------------------------------
static constexpr int FA_SMEM =
    (64 * 64 + 64 * 65 + 64 * 64 + 64 * 64) * (int)sizeof(float);  // 65792 B

__global__ __launch_bounds__(256, 2)
void flash_attn_kernel(const float* __restrict__ qkv, float* __restrict__ attout)
{
    float* fsm = reinterpret_cast<float*>(dynsmem);
    float* Qs  = fsm;
    float* KsT = Qs  + 64 * 64;
    float* Vs  = KsT + 64 * 65;
    float* Ps  = Vs  + 64 * 64;

    const int tid = threadIdx.x;
    const int ty  = tid >> 4;
    const int tx  = tid & 15;
    const int qtile = blockIdx.x;
    const int bh    = blockIdx.y;
    const int b = bh >> 4, h = bh & 15;

    const size_t base = (size_t)b * N_ * QKV;
    const int hcol = h * HD;
    const float scale = 0.125f;

    #pragma unroll
    for (int i = 0; i < 16; i++) {
        const int e = tid + i * 256;
        const int r = e >> 6, d = e & 63;
        Qs[r * 64 + d] = qkv[base + (size_t)(qtile * 64 + r) * QKV + 1024 + hcol + d] * scale;
    }

    float o[4][4], m[4], l[4];
    #pragma unroll
    for (int i = 0; i < 4; i++) {
        m[i] = -1e30f; l[i] = 0.0f;
        #pragma unroll
        for (int j = 0; j < 4; j++) o[i][j] = 0.0f;
    }

    for (int kt = 0; kt < 16; kt++) {
        __syncthreads();
        #pragma unroll
        for (int i = 0; i < 16; i++) {
            const int e = tid + i * 256;
            const int r = e >> 6, d = e & 63;
            const size_t rowoff = base + (size_t)(kt * 64 + r) * QKV + hcol + d;
            KsT[d * 65 + r] = qkv[rowoff];
            Vs [r * 64 + d] = qkv[rowoff + 2048];
        }
        __syncthreads();

        float s[4][4];
        #pragma unroll
        for (int i = 0; i < 4; i++)
            #pragma unroll
            for (int j = 0; j < 4; j++) s[i][j] = 0.0f;

        #pragma unroll 8
        for (int k = 0; k < 64; k++) {
            float a[4], bb[4];
            #pragma unroll
            for (int i = 0; i < 4; i++) a[i]  = Qs[(ty * 4 + i) * 64 + k];
            #pragma unroll
            for (int j = 0; j < 4; j++) bb[j] = KsT[k * 65 + tx * 4 + j];
            #pragma unroll
            for (int i = 0; i < 4; i++)
                #pragma unroll
                for (int j = 0; j < 4; j++)
                    s[i][j] = fmaf(a[i], bb[j], s[i][j]);
        }

        #pragma unroll
        for (int i = 0; i < 4; i++) {
            float tmax = fmaxf(fmaxf(s[i][0], s[i][1]), fmaxf(s[i][2], s[i][3]));
            #pragma unroll
            for (int off = 8; off >= 1; off >>= 1)
                tmax = fmaxf(tmax, __shfl_xor_sync(0xffffffffu, tmax, off, 32));
            const float mnew = fmaxf(m[i], tmax);
            const float corr = __expf(m[i] - mnew);
            m[i] = mnew;
            float tsum = 0.0f;
            #pragma unroll
            for (int j = 0; j < 4; j++) {
                s[i][j] = __expf(s[i][j] - mnew);
                tsum += s[i][j];
            }
            #pragma unroll
            for (int off = 8; off >= 1; off >>= 1)
                tsum += __shfl_xor_sync(0xffffffffu, tsum, off, 32);
            l[i] = l[i] * corr + tsum;
            #pragma unroll
            for (int j = 0; j < 4; j++) o[i][j] *= corr;
        }

        #pragma unroll
        for (int i = 0; i < 4; i++) {
            float4 v = make_float4(s[i][0], s[i][1], s[i][2], s[i][3]);
            *reinterpret_cast<float4*>(&Ps[(ty * 4 + i) * 64 + tx * 4]) = v;
        }
        __syncthreads();

        #pragma unroll 8
        for (int kk = 0; kk < 64; kk++) {
            float p[4];
            #pragma unroll
            for (int i = 0; i < 4; i++) p[i] = Ps[(ty * 4 + i) * 64 + kk];
            const float4 vv = *reinterpret_cast<const float4*>(&Vs[kk * 64 + tx * 4]);
            const float vb[4] = { vv.x, vv.y, vv.z, vv.w };
            #pragma unroll
            for (int i = 0; i < 4; i++)
                #pragma unroll
                for (int j = 0; j < 4; j++)
                    o[i][j] = fmaf(p[i], vb[j], o[i][j]);
        }
    }

    #pragma unroll
    for (int i = 0; i < 4; i++) {
        const float inv = 1.0f / l[i];
        const int n = qtile * 64 + ty * 4 + i;
        float4 v = make_float4(o[i][0] * inv, o[i][1] * inv,
                               o[i][2] * inv, o[i][3] * inv);
        *reinterpret_cast<float4*>(
            &attout[((size_t)b * N_ + n) * EMB + hcol + tx * 4]) = v;
    }
}

// ---------------------------------------------------------------------------
extern "C" void kernel_launch(void* const* d_in, const int* in_sizes, int n_in,
                              void* d_out, int out_size)
{
    const float* x     = (const float*)d_in[0];
    const float* W_qkv = (const float*)d_in[1];
    const float* b_qkv = (const float*)d_in[2];
    const float* W_out = (const float*)d_in[3];
    const float* b_out = (const float*)d_in[4];
    float* out = (float*)d_out;

    float *qkvbuf = nullptr, *attbuf = nullptr;
    __nv_bfloat16 *xh, *xl, *wqh, *wql, *woh, *wol, *ath, *atl;
    cudaGetSymbolAddress((void**)&qkvbuf, g_qkv);
    cudaGetSymbolAddress((void**)&attbuf, g_att);
    cudaGetSymbolAddress((void**)&xh,  g_xh);
    cudaGetSymbolAddress((void**)&xl,  g_xl);
    cudaGetSymbolAddress((void**)&wqh, g_WqTh);
    cudaGetSymbolAddress((void**)&wql, g_WqTl);
    cudaGetSymbolAddress((void**)&woh, g_WoTh);
    cudaGetSymbolAddress((void**)&wol, g_WoTl);
    cudaGetSymbolAddress((void**)&ath, g_ath);
    cudaGetSymbolAddress((void**)&atl, g_atl);

    cudaFuncSetAttribute(flash_attn_kernel,
                         cudaFuncAttributeMaxDynamicSharedMemorySize, FA_SMEM);

    // 0) operand conversions
    split_kernel<<<(M_ * EMB / 4 + 255) / 256, 256>>>(x, xh, xl, M_ * EMB / 4);
    transpose_split<<<dim3(QKV / 32, EMB / 32), dim3(32, 8)>>>(W_qkv, wqh, wql, EMB, QKV);
    transpose_split<<<dim3(EMB / 32, EMB / 32), dim3(32, 8)>>>(W_out, woh, wol, EMB, EMB);

    // 1) QKV projection (HMMA): [4096,1024] @ [1024,3072] + b_qkv
    gemm_hmma_split<<<dim3(QKV / 128, M_ / 128), 256>>>(
        xh, xl, wqh, wql, b_qkv, qkvbuf, QKV);

    // 2) attention
    flash_attn_kernel<<<dim3(16, B_ * H_), 256, FA_SMEM>>>(qkvbuf, attbuf);

    // 3) output projection (HMMA): [4096,1024] @ [1024,1024] + b_out
    split_kernel<<<(M_ * EMB / 4 + 255) / 256, 256>>>(attbuf, ath, atl, M_ * EMB / 4);
    gemm_hmma_split<<<dim3(EMB / 128, M_ / 128), 256>>>(
        ath, atl, woh, wol, b_out, out, EMB);
}

// round 11
// speedup vs baseline: 1.7890x; 1.3511x over previous
#include <cuda_runtime.h>
#include <cuda_bf16.h>
#include <cstdint>

// Problem constants
static constexpr int B_   = 4;
static constexpr int N_   = 1024;
static constexpr int EMB  = 1024;
static constexpr int H_   = 16;
static constexpr int HD   = 64;
static constexpr int QKV  = 3 * H_ * HD;   // 3072
static constexpr int M_   = B_ * N_;       // 4096

// ---------------------------------------------------------------------------
// Scratch (device globals; no runtime allocation allowed)
// ---------------------------------------------------------------------------
__device__ __nv_bfloat16 g_xh[M_ * EMB];          // x hi
__device__ __nv_bfloat16 g_xl[M_ * EMB];          // x lo
__device__ __nv_bfloat16 g_WqTh[QKV * EMB];       // W_qkv^T hi
__device__ __nv_bfloat16 g_WqTl[QKV * EMB];
__device__ __nv_bfloat16 g_WoTh[EMB * EMB];       // W_out^T hi
__device__ __nv_bfloat16 g_WoTl[EMB * EMB];
__device__ __nv_bfloat16 g_qkh[M_ * QKV];         // qkv hi (Q third pre-scaled)
__device__ __nv_bfloat16 g_qkl[M_ * QKV];         // qkv lo
__device__ __nv_bfloat16 g_ath[M_ * EMB];         // attention out hi
__device__ __nv_bfloat16 g_atl[M_ * EMB];         // attention out lo

// Dynamic smem (attention only)
extern __shared__ __align__(1024) uint8_t dynsmem[];

// ---------------------------------------------------------------------------
// Helpers
// ---------------------------------------------------------------------------
__device__ __forceinline__ uint32_t smem_to_u32(const void* smem_ptr) {
    uint32_t addr;
    asm("{ .reg .u64 tmp; cvta.to.shared.u64 tmp, %1; cvt.u32.u64 %0, tmp; }"
        : "=r"(addr) : "l"(smem_ptr));
    return addr;
}

#define CP_ASYNC_16(smem_u32, gptr) \
    asm volatile("cp.async.cg.shared.global [%0], [%1], 16;" \
                 :: "r"(smem_u32), "l"(gptr) : "memory")
#define CP_ASYNC_COMMIT() asm volatile("cp.async.commit_group;" ::: "memory")
#define CP_ASYNC_WAIT0()  asm volatile("cp.async.wait_group 0;" ::: "memory")
#define CP_ASYNC_WAIT1()  asm volatile("cp.async.wait_group 1;" ::: "memory")
#define CP_ASYNC_WAIT2()  asm volatile("cp.async.wait_group 2;" ::: "memory")

#define LDSM_X4(r0, r1, r2, r3, addr) \
    asm volatile("ldmatrix.sync.aligned.m8n8.x4.shared.b16 {%0,%1,%2,%3}, [%4];" \
                 : "=r"(r0), "=r"(r1), "=r"(r2), "=r"(r3) : "r"(addr))
#define LDSM_X4_T(r0, r1, r2, r3, addr) \
    asm volatile("ldmatrix.sync.aligned.m8n8.x4.trans.shared.b16 {%0,%1,%2,%3}, [%4];" \
                 : "=r"(r0), "=r"(r1), "=r"(r2), "=r"(r3) : "r"(addr))

__device__ __forceinline__ void mma16816(float& c0, float& c1, float& c2, float& c3,
                                         uint32_t a0, uint32_t a1, uint32_t a2, uint32_t a3,
                                         uint32_t b0, uint32_t b1) {
    asm volatile(
        "mma.sync.aligned.m16n8k16.row.col.f32.bf16.bf16.f32 "
        "{%0,%1,%2,%3}, {%4,%5,%6,%7}, {%8,%9}, {%0,%1,%2,%3};"
        : "+f"(c0), "+f"(c1), "+f"(c2), "+f"(c3)
        : "r"(a0), "r"(a1), "r"(a2), "r"(a3), "r"(b0), "r"(b1));
}

// pack two f32 to bf16x2 (lo = first elem)
__device__ __forceinline__ uint32_t pack_bf16x2(float lo, float hi) {
    uint32_t d;
    asm("cvt.rn.bf16x2.f32 %0, %1, %2;" : "=r"(d) : "f"(hi), "f"(lo));
    return d;
}

// ---------------------------------------------------------------------------
// Elementwise fp32 -> (bf16 hi, bf16 lo) split
// ---------------------------------------------------------------------------
__global__ void split_kernel(const float* __restrict__ in,
                             __nv_bfloat16* __restrict__ hi,
                             __nv_bfloat16* __restrict__ lo, int n4)
{
    const int i = blockIdx.x * blockDim.x + threadIdx.x;
    if (i >= n4) return;
    const float4 v = reinterpret_cast<const float4*>(in)[i];
    __nv_bfloat16 h0 = __float2bfloat16(v.x);
    __nv_bfloat16 h1 = __float2bfloat16(v.y);
    __nv_bfloat16 h2 = __float2bfloat16(v.z);
    __nv_bfloat16 h3 = __float2bfloat16(v.w);
    __nv_bfloat16 l0 = __float2bfloat16(v.x - __bfloat162float(h0));
    __nv_bfloat16 l1 = __float2bfloat16(v.y - __bfloat162float(h1));
    __nv_bfloat16 l2 = __float2bfloat16(v.z - __bfloat162float(h2));
    __nv_bfloat16 l3 = __float2bfloat16(v.w - __bfloat162float(h3));
    __nv_bfloat162* H = reinterpret_cast<__nv_bfloat162*>(hi);
    __nv_bfloat162* L = reinterpret_cast<__nv_bfloat162*>(lo);
    H[2*i]   = __nv_bfloat162(h0, h1);
    H[2*i+1] = __nv_bfloat162(h2, h3);
    L[2*i]   = __nv_bfloat162(l0, l1);
    L[2*i+1] = __nv_bfloat162(l2, l3);
}

// ---------------------------------------------------------------------------
// W [Kdim][Ndim] fp32 -> transposed split bf16 Th/Tl [Ndim][Kdim]
// ---------------------------------------------------------------------------
__global__ void transpose_split(const float* __restrict__ W,
                                __nv_bfloat16* __restrict__ Th,
                                __nv_bfloat16* __restrict__ Tl,
                                int Kdim, int Ndim)
{
    __shared__ float t[32][33];
    const int nb = blockIdx.x * 32;
    const int kb = blockIdx.y * 32;
    const int tx = threadIdx.x;
    const int ty = threadIdx.y;   // 0..7
    #pragma unroll
    for (int i = 0; i < 32; i += 8)
        t[ty + i][tx] = W[(size_t)(kb + ty + i) * Ndim + nb + tx];
    __syncthreads();
    #pragma unroll
    for (int i = 0; i < 32; i += 8) {
        const float v = t[tx][ty + i];
        const __nv_bfloat16 h = __float2bfloat16(v);
        const __nv_bfloat16 l = __float2bfloat16(v - __bfloat162float(h));
        const size_t o = (size_t)(nb + ty + i) * Kdim + kb + tx;
        Th[o] = h;
        Tl[o] = l;
    }
}

// ---------------------------------------------------------------------------
// HMMA split GEMM: C[M,N] = (Ah+Al)[M,1024] @ (Bh+Bl)^T (+bias)
//   EPI=0: write fp32 C. EPI=1: write bf16 hi/lo (Q third cols [1024,2048)
//   scaled by 0.125 after bias).
//   CTA 128x128, BK=32, 8 warps @ 64x32, 3-stage cp.async, ldmatrix frags.
// ---------------------------------------------------------------------------
static constexpr int GPITCH = 40;  // bf16 per smem row (32 data + 8 pad)

template <int EPI>
__global__ __launch_bounds__(256, 2)
void gemm_hmma_split(const __nv_bfloat16* __restrict__ Ah,
                     const __nv_bfloat16* __restrict__ Al,
                     const __nv_bfloat16* __restrict__ Bh,
                     const __nv_bfloat16* __restrict__ Bl,
                     const float* __restrict__ bias,
                     float* __restrict__ Cf,
                     __nv_bfloat16* __restrict__ Ch,
                     __nv_bfloat16* __restrict__ Cl,
                     int N)
{
    __shared__ __align__(16) __nv_bfloat16 sA[3][128][GPITCH];
    __shared__ __align__(16) __nv_bfloat16 sB[3][128][GPITCH];

    const int tid  = threadIdx.x;
    const int wid  = tid >> 5;
    const int lane = tid & 31;
    const int wm   = wid & 1;          // rows wm*64
    const int wn   = wid >> 1;         // cols wn*32
    const int rowBase = blockIdx.y * 128;
    const int colBase = blockIdx.x * 128;
    constexpr int K = 1024;
    constexpr int NCHUNK = 96;         // 3 passes x 32 chunks of BK=32

    const uint32_t aBase = smem_to_u32(&sA[0][0][0]);
    const uint32_t bBase = smem_to_u32(&sB[0][0][0]);
    constexpr uint32_t STAGE = 128 * GPITCH * 2;  // 10240 B

    const int ldRow = tid >> 1;          // 0..127
    const int ldCol = (tid & 1) * 16;    // bf16 col 0 or 16

    float acc[4][4][4];
    #pragma unroll
    for (int mt = 0; mt < 4; mt++)
        #pragma unroll
        for (int nt = 0; nt < 4; nt++)
            #pragma unroll
            for (int q = 0; q < 4; q++) acc[mt][nt][q] = 0.0f;

    auto issue_loads = [&](int c) {
        const int buf = c % 3;
        const int p  = c >> 5;               // pass 0,1,2
        const int ks = (c & 31) * 32;        // K element offset
        const __nv_bfloat16* Ap = (p == 1) ? Al : Ah;
        const __nv_bfloat16* Bp = (p == 2) ? Bl : Bh;
        const __nv_bfloat16* ga = Ap + (size_t)(rowBase + ldRow) * K + ks + ldCol;
        const __nv_bfloat16* gb = Bp + (size_t)(colBase + ldRow) * K + ks + ldCol;
        const uint32_t sa = aBase + buf * STAGE + (ldRow * GPITCH + ldCol) * 2;
        const uint32_t sb = bBase + buf * STAGE + (ldRow * GPITCH + ldCol) * 2;
        CP_ASYNC_16(sa,      ga);
        CP_ASYNC_16(sa + 16, ga + 8);
        CP_ASYNC_16(sb,      gb);
        CP_ASYNC_16(sb + 16, gb + 8);
        CP_ASYNC_COMMIT();
    };

    issue_loads(0);
    issue_loads(1);

    for (int c = 0; c < NCHUNK; c++) {
        const int buf = c % 3;
        if (c + 2 < NCHUNK) issue_loads(c + 2);
        if (c + 2 < NCHUNK)       { CP_ASYNC_WAIT2(); }
        else if (c + 1 < NCHUNK)  { CP_ASYNC_WAIT1(); }
        else                      { CP_ASYNC_WAIT0(); }
        __syncthreads();

        const uint32_t aS = aBase + buf * STAGE;
        const uint32_t bS = bBase + buf * STAGE;
        const int fr = lane & 15;            // ldmatrix row within 16
        const int fc = (lane >> 4) * 8;      // ldmatrix col half

        #pragma unroll
        for (int kk = 0; kk < 32; kk += 16) {
            uint32_t af[4][4];
            #pragma unroll
            for (int mt = 0; mt < 4; mt++) {
                const int r = wm * 64 + mt * 16 + fr;
                LDSM_X4(af[mt][0], af[mt][1], af[mt][2], af[mt][3],
                        aS + (r * GPITCH + kk + fc) * 2);
            }
            uint32_t bf[4][2];
            #pragma unroll
            for (int np = 0; np < 2; np++) {
                const int r = wn * 32 + np * 16 + fr;
                uint32_t b0, b1, b2, b3;
                LDSM_X4(b0, b1, b2, b3, bS + (r * GPITCH + kk + fc) * 2);
                bf[np*2][0] = b0; bf[np*2+1][0] = b1;
                bf[np*2][1] = b2; bf[np*2+1][1] = b3;
            }
            #pragma unroll
            for (int mt = 0; mt < 4; mt++)
                #pragma unroll
                for (int nt = 0; nt < 4; nt++)
                    mma16816(acc[mt][nt][0], acc[mt][nt][1],
                             acc[mt][nt][2], acc[mt][nt][3],
                             af[mt][0], af[mt][1], af[mt][2], af[mt][3],
                             bf[nt][0], bf[nt][1]);
        }
        __syncthreads();
    }

    // Epilogue
    #pragma unroll
    for (int mt = 0; mt < 4; mt++) {
        const int r0 = rowBase + wm * 64 + mt * 16 + (lane >> 2);
        #pragma unroll
        for (int nt = 0; nt < 4; nt++) {
            const int col = colBase + wn * 32 + nt * 8 + (lane & 3) * 2;
            const float b0 = bias[col], b1 = bias[col + 1];
            float v0 = acc[mt][nt][0] + b0, v1 = acc[mt][nt][1] + b1;
            float v2 = acc[mt][nt][2] + b0, v3 = acc[mt][nt][3] + b1;
            if (EPI == 1) {
                // scale Q third (cols [1024,2048)) by 1/sqrt(hd)
                const float sc = (col >= 1024 && col < 2048) ? 0.125f : 1.0f;
                v0 *= sc; v1 *= sc; v2 *= sc; v3 *= sc;
                const __nv_bfloat16 h0 = __float2bfloat16(v0);
                const __nv_bfloat16 h1 = __float2bfloat16(v1);
                const __nv_bfloat16 h2 = __float2bfloat16(v2);
                const __nv_bfloat16 h3 = __float2bfloat16(v3);
                *reinterpret_cast<__nv_bfloat162*>(&Ch[(size_t)r0 * N + col]) =
                    __nv_bfloat162(h0, h1);
                *reinterpret_cast<__nv_bfloat162*>(&Ch[(size_t)(r0 + 8) * N + col]) =
                    __nv_bfloat162(h2, h3);
                *reinterpret_cast<__nv_bfloat162*>(&Cl[(size_t)r0 * N + col]) =
                    __nv_bfloat162(__float2bfloat16(v0 - __bfloat162float(h0)),
                                   __float2bfloat16(v1 - __bfloat162float(h1)));
                *reinterpret_cast<__nv_bfloat162*>(&Cl[(size_t)(r0 + 8) * N + col]) =
                    __nv_bfloat162(__float2bfloat16(v2 - __bfloat162float(h2)),
                                   __float2bfloat16(v3 - __bfloat162float(h3)));
            } else {
                *reinterpret_cast<float2*>(&Cf[(size_t)r0 * N + col]) =
                    make_float2(v0, v1);
                *reinterpret_cast<float2*>(&Cf[(size_t)(r0 + 8) * N + col]) =
                    make_float2(v2, v3);
            }
        }
    }
}

// ---------------------------------------------------------------------------
// HMMA flash attention. CTA = (qtile of 128 rows, b, h). 8 warps x 16 rows.
// S = Q K^T and O += P V both via bf16 hi/lo 3-pass m16n8k16.
// qkv thirds in g_qkh/g_qkl: [0,1024)=K, [1024,2048)=Q (pre-scaled), [2048,3072)=V.
// ---------------------------------------------------------------------------
static constexpr int APITCH = 72;                        // bf16 pitch
static constexpr int ATILE  = 128 * APITCH * 2;          // 18432 B per array
static constexpr int AT_SMEM = 4 * ATILE;                // 73728 B

__global__ __launch_bounds__(256, 1)
void flash_attn_hmma(const __nv_bfloat16* __restrict__ QKVh,
                     const __nv_bfloat16* __restrict__ QKVl,
                     __nv_bfloat16* __restrict__ Oh,
                     __nv_bfloat16* __restrict__ Ol)
{
    const uint32_t sb  = smem_to_u32(dynsmem);
    const uint32_t sKh = sb;
    const uint32_t sKl = sb + ATILE;
    const uint32_t sVh = sb + 2 * ATILE;
    const uint32_t sVl = sb + 3 * ATILE;

    const int tid  = threadIdx.x;
    const int w    = tid >> 5;
    const int lane = tid & 31;
    const int qt = blockIdx.x;          // 0..7
    const int bh = blockIdx.y;          // 0..63
    const int b = bh >> 4, h = bh & 15;
    const size_t baseRow = (size_t)b * N_;
    const int hcol = h * HD;

    const int ldr = tid >> 1;               // 0..127
    const int ldc = (tid & 1) * 32;         // bf16 col base

    // ---- stage Q tile (128x64 hi/lo) through sKh/sKl, ldmatrix to regs ----
    {
        const size_t grow = (baseRow + qt * 128 + ldr) * QKV + 1024 + hcol + ldc;
        #pragma unroll
        for (int s = 0; s < 4; s++) {
            const uint32_t so = (ldr * APITCH + ldc + s * 8) * 2;
            CP_ASYNC_16(sKh + so, QKVh + grow + s * 8);
            CP_ASYNC_16(sKl + so, QKVl + grow + s * 8);
        }
        CP_ASYNC_COMMIT();
        CP_ASYNC_WAIT0();
    }
    __syncthreads();

    uint32_t qh[4][4], ql[4][4];
    {
        const int row = w * 16 + (lane & 15);
        #pragma unroll
        for (int kc = 0; kc < 4; kc++) {
            const int col = kc * 16 + (lane >> 4) * 8;
            LDSM_X4(qh[kc][0], qh[kc][1], qh[kc][2], qh[kc][3],
                    sKh + (row * APITCH + col) * 2);
            LDSM_X4(ql[kc][0], ql[kc][1], ql[kc][2], ql[kc][3],
                    sKl + (row * APITCH + col) * 2);
        }
    }

    float o[8][4];
    #pragma unroll
    for (int nt = 0; nt < 8; nt++)
        #pragma unroll
        for (int q = 0; q < 4; q++) o[nt][q] = 0.0f;
    float m0 = -1e30f, m1 = -1e30f, l0 = 0.0f, l1 = 0.0f;

    for (int kt = 0; kt < 8; kt++) {
        __syncthreads();   // prior compute done reading smem
        {
            const size_t grow = (baseRow + kt * 128 + ldr) * QKV + hcol + ldc;
            #pragma unroll
            for (int s = 0; s < 4; s++) {
                const uint32_t so = (ldr * APITCH + ldc + s * 8) * 2;
                const size_t go = grow + s * 8;
                CP_ASYNC_16(sKh + so, QKVh + go);          // K third
                CP_ASYNC_16(sKl + so, QKVl + go);
                CP_ASYNC_16(sVh + so, QKVh + go + 2048);   // V third
                CP_ASYNC_16(sVl + so, QKVl + go + 2048);
            }
            CP_ASYNC_COMMIT();
            CP_ASYNC_WAIT0();
        }
        __syncthreads();

        // ---- S = Q K^T (16 rows x 128 cols per warp), 3 passes ----
        float s[16][4];
        #pragma unroll
        for (int nt = 0; nt < 16; nt++)
            #pragma unroll
            for (int q = 0; q < 4; q++) s[nt][q] = 0.0f;

        const int fr = lane & 15;
        const int fc8 = (lane >> 4) * 8;
        #pragma unroll
        for (int kc = 0; kc < 4; kc++) {
            const int col = kc * 16 + fc8;
            #pragma unroll
            for (int np = 0; np < 8; np++) {
                uint32_t b0, b1, b2, b3;
                LDSM_X4(b0, b1, b2, b3, sKh + ((np * 16 + fr) * APITCH + col) * 2);
                mma16816(s[2*np][0], s[2*np][1], s[2*np][2], s[2*np][3],
                         qh[kc][0], qh[kc][1], qh[kc][2], qh[kc][3], b0, b2);
                mma16816(s[2*np+1][0], s[2*np+1][1], s[2*np+1][2], s[2*np+1][3],
                         qh[kc][0], qh[kc][1], qh[kc][2], qh[kc][3], b1, b3);
                mma16816(s[2*np][0], s[2*np][1], s[2*np][2], s[2*np][3],
                         ql[kc][0], ql[kc][1], ql[kc][2], ql[kc][3], b0, b2);
                mma16816(s[2*np+1][0], s[2*np+1][1], s[2*np+1][2], s[2*np+1][3],
                         ql[kc][0], ql[kc][1], ql[kc][2], ql[kc][3], b1, b3);
                LDSM_X4(b0, b1, b2, b3, sKl + ((np * 16 + fr) * APITCH + col) * 2);
                mma16816(s[2*np][0], s[2*np][1], s[2*np][2], s[2*np][3],
                         qh[kc][0], qh[kc][1], qh[kc][2], qh[kc][3], b0, b2);
                mma16816(s[2*np+1][0], s[2*np+1][1], s[2*np+1][2], s[2*np+1][3],
                         qh[kc][0], qh[kc][1], qh[kc][2], qh[kc][3], b1, b3);
            }
        }

        // ---- online softmax (rows r = lane>>2 and r+8; warp-local) ----
        float tm0 = -1e30f, tm1 = -1e30f;
        #pragma unroll
        for (int nt = 0; nt < 16; nt++) {
            tm0 = fmaxf(tm0, fmaxf(s[nt][0], s[nt][1]));
            tm1 = fmaxf(tm1, fmaxf(s[nt][2], s[nt][3]));
        }
        tm0 = fmaxf(tm0, __shfl_xor_sync(0xffffffffu, tm0, 1));
        tm0 = fmaxf(tm0, __shfl_xor_sync(0xffffffffu, tm0, 2));
        tm1 = fmaxf(tm1, __shfl_xor_sync(0xffffffffu, tm1, 1));
        tm1 = fmaxf(tm1, __shfl_xor_sync(0xffffffffu, tm1, 2));
        const float mn0 = fmaxf(m0, tm0), mn1 = fmaxf(m1, tm1);
        const float cr0 = __expf(m0 - mn0), cr1 = __expf(m1 - mn1);
        m0 = mn0; m1 = mn1;
        float ts0 = 0.0f, ts1 = 0.0f;
        #pragma unroll
        for (int nt = 0; nt < 16; nt++) {
            s[nt][0] = __expf(s[nt][0] - mn0);
            s[nt][1] = __expf(s[nt][1] - mn0);
            s[nt][2] = __expf(s[nt][2] - mn1);
            s[nt][3] = __expf(s[nt][3] - mn1);
            ts0 += s[nt][0] + s[nt][1];
            ts1 += s[nt][2] + s[nt][3];
        }
        ts0 += __shfl_xor_sync(0xffffffffu, ts0, 1);
        ts0 += __shfl_xor_sync(0xffffffffu, ts0, 2);
        ts1 += __shfl_xor_sync(0xffffffffu, ts1, 1);
        ts1 += __shfl_xor_sync(0xffffffffu, ts1, 2);
        l0 = l0 * cr0 + ts0;
        l1 = l1 * cr1 + ts1;
        #pragma unroll
        for (int nt = 0; nt < 8; nt++) {
            o[nt][0] *= cr0; o[nt][1] *= cr0;
            o[nt][2] *= cr1; o[nt][3] *= cr1;
        }

        // ---- O += P V (3 passes); P A-frags built from s accumulators ----
        #pragma unroll
        for (int kc = 0; kc < 8; kc++) {
            // hi parts + residuals
            uint32_t pa_h[4], pa_l[4];
            #pragma unroll
            for (int half = 0; half < 2; half++) {
                const int nt = 2 * kc + half;
                const __nv_bfloat16 ha = __float2bfloat16(s[nt][0]);
                const __nv_bfloat16 hb = __float2bfloat16(s[nt][1]);
                const __nv_bfloat16 hc = __float2bfloat16(s[nt][2]);
                const __nv_bfloat16 hd_ = __float2bfloat16(s[nt][3]);
                __nv_bfloat162 t0(ha, hb), t1(hc, hd_);
                pa_h[half * 2]     = *reinterpret_cast<uint32_t*>(&t0);
                pa_h[half * 2 + 1] = *reinterpret_cast<uint32_t*>(&t1);
                pa_l[half * 2] = pack_bf16x2(s[nt][0] - __bfloat162float(ha),
                                             s[nt][1] - __bfloat162float(hb));
                pa_l[half * 2 + 1] = pack_bf16x2(s[nt][2] - __bfloat162float(hc),
                                                 s[nt][3] - __bfloat162float(hd_));
            }
            const int vrow = kc * 16 + fr;
            #pragma unroll
            for (int np = 0; np < 4; np++) {
                const int vcol = np * 16 + fc8;
                uint32_t b0, b1, b2, b3;
                LDSM_X4_T(b0, b1, b2, b3, sVh + (vrow * APITCH + vcol) * 2);
                mma16816(o[2*np][0], o[2*np][1], o[2*np][2], o[2*np][3],
                         pa_h[0], pa_h[1], pa_h[2], pa_h[3], b0, b1);
                mma16816(o[2*np+1][0], o[2*np+1][1], o[2*np+1][2], o[2*np+1][3],
                         pa_h[0], pa_h[1], pa_h[2], pa_h[3], b2, b3);
                mma16816(o[2*np][0], o[2*np][1], o[2*np][2], o[2*np][3],
                         pa_l[0], pa_l[1], pa_l[2], pa_l[3], b0, b1);
                mma16816(o[2*np+1][0], o[2*np+1][1], o[2*np+1][2], o[2*np+1][3],
                         pa_l[0], pa_l[1], pa_l[2], pa_l[3], b2, b3);
                LDSM_X4_T(b0, b1, b2, b3, sVl + (vrow * APITCH + vcol) * 2);
                mma16816(o[2*np][0], o[2*np][1], o[2*np][2], o[2*np][3],
                         pa_h[0], pa_h[1], pa_h[2], pa_h[3], b0, b1);
                mma16816(o[2*np+1][0], o[2*np+1][1], o[2*np+1][2], o[2*np+1][3],
                         pa_h[0], pa_h[1], pa_h[2], pa_h[3], b2, b3);
            }
        }
    }

    // ---- epilogue: O /= l, write bf16 hi/lo ----
    const float inv0 = 1.0f / l0, inv1 = 1.0f / l1;
    const size_t r0 = baseRow + qt * 128 + w * 16 + (lane >> 2);
    #pragma unroll
    for (int nt = 0; nt < 8; nt++) {
        const int col = hcol + nt * 8 + (lane & 3) * 2;
        const float v0 = o[nt][0] * inv0, v1 = o[nt][1] * inv0;
        const float v2 = o[nt][2] * inv1, v3 = o[nt][3] * inv1;
        const __nv_bfloat16 h0 = __float2bfloat16(v0);
        const __nv_bfloat16 h1 = __float2bfloat16(v1);
        const __nv_bfloat16 h2 = __float2bfloat16(v2);
        const __nv_bfloat16 h3 = __float2bfloat16(v3);
        *reinterpret_cast<__nv_bfloat162*>(&Oh[r0 * EMB + col]) = __nv_bfloat162(h0, h1);
        *reinterpret_cast<__nv_bfloat162*>(&Oh[(r0 + 8) * EMB + col]) = __nv_bfloat162(h2, h3);
        *reinterpret_cast<__nv_bfloat162*>(&Ol[r0 * EMB + col]) =
            __nv_bfloat162(__float2bfloat16(v0 - __bfloat162float(h0)),
                           __float2bfloat16(v1 - __bfloat162float(h1)));
        *reinterpret_cast<__nv_bfloat162*>(&Ol[(r0 + 8) * EMB + col]) =
            __nv_bfloat162(__float2bfloat16(v2 - __bfloat162float(h2)),
                           __float2bfloat16(v3 - __bfloat162float(h3)));
    }
}

// ---------------------------------------------------------------------------
extern "C" void kernel_launch(void* const* d_in, const int* in_sizes, int n_in,
                              void* d_out, int out_size)
{
    const float* x     = (const float*)d_in[0];
    const float* W_qkv = (const float*)d_in[1];
    const float* b_qkv = (const float*)d_in[2];
    const float* W_out = (const float*)d_in[3];
    const float* b_out = (const float*)d_in[4];
    float* out = (float*)d_out;

    __nv_bfloat16 *xh, *xl, *wqh, *wql, *woh, *wol, *qkh, *qkl, *ath, *atl;
    cudaGetSymbolAddress((void**)&xh,  g_xh);
    cudaGetSymbolAddress((void**)&xl,  g_xl);
    cudaGetSymbolAddress((void**)&wqh, g_WqTh);
    cudaGetSymbolAddress((void**)&wql, g_WqTl);
    cudaGetSymbolAddress((void**)&woh, g_WoTh);
    cudaGetSymbolAddress((void**)&wol, g_WoTl);
    cudaGetSymbolAddress((void**)&qkh, g_qkh);
    cudaGetSymbolAddress((void**)&qkl, g_qkl);
    cudaGetSymbolAddress((void**)&ath, g_ath);
    cudaGetSymbolAddress((void**)&atl, g_atl);

    cudaFuncSetAttribute(flash_attn_hmma,
                         cudaFuncAttributeMaxDynamicSharedMemorySize, AT_SMEM);

    // 0) operand conversions
    split_kernel<<<(M_ * EMB / 4 + 255) / 256, 256>>>(x, xh, xl, M_ * EMB / 4);
    transpose_split<<<dim3(QKV / 32, EMB / 32), dim3(32, 8)>>>(W_qkv, wqh, wql, EMB, QKV);
    transpose_split<<<dim3(EMB / 32, EMB / 32), dim3(32, 8)>>>(W_out, woh, wol, EMB, EMB);

    // 1) QKV projection -> bf16 hi/lo qkv (Q third pre-scaled by 0.125)
    gemm_hmma_split<1><<<dim3(QKV / 128, M_ / 128), 256>>>(
        xh, xl, wqh, wql, b_qkv, nullptr, qkh, qkl, QKV);

    // 2) attention (tensorized) -> bf16 hi/lo attention output
    flash_attn_hmma<<<dim3(8, B_ * H_), 256, AT_SMEM>>>(qkh, qkl, ath, atl);

    // 3) output projection -> fp32 out
    gemm_hmma_split<0><<<dim3(EMB / 128, M_ / 128), 256>>>(
        ath, atl, woh, wol, b_out, out, nullptr, nullptr, EMB);
}

// round 14
// speedup vs baseline: 1.8341x; 1.0252x over previous
#include <cuda_runtime.h>
#include <cuda_bf16.h>
#include <cstdint>

// Problem constants
static constexpr int B_   = 4;
static constexpr int N_   = 1024;
static constexpr int EMB  = 1024;
static constexpr int H_   = 16;
static constexpr int HD   = 64;
static constexpr int QKV  = 3 * H_ * HD;   // 3072
static constexpr int M_   = B_ * N_;       // 4096

// ---------------------------------------------------------------------------
// Scratch (device globals; no runtime allocation allowed)
// ---------------------------------------------------------------------------
__device__ __nv_bfloat16 g_xh[M_ * EMB];
__device__ __nv_bfloat16 g_xl[M_ * EMB];
__device__ __nv_bfloat16 g_WqTh[QKV * EMB];
__device__ __nv_bfloat16 g_WqTl[QKV * EMB];
__device__ __nv_bfloat16 g_WoTh[EMB * EMB];
__device__ __nv_bfloat16 g_WoTl[EMB * EMB];
__device__ __nv_bfloat16 g_qkh[M_ * QKV];         // qkv hi (Q third pre-scaled)
__device__ __nv_bfloat16 g_qkl[M_ * QKV];
__device__ __nv_bfloat16 g_ath[M_ * EMB];
__device__ __nv_bfloat16 g_atl[M_ * EMB];

extern __shared__ __align__(1024) uint8_t dynsmem[];

// ---------------------------------------------------------------------------
// Helpers
// ---------------------------------------------------------------------------
__device__ __forceinline__ uint32_t smem_to_u32(const void* smem_ptr) {
    uint32_t addr;
    asm("{ .reg .u64 tmp; cvta.to.shared.u64 tmp, %1; cvt.u32.u64 %0, tmp; }"
        : "=r"(addr) : "l"(smem_ptr));
    return addr;
}

#define CP_ASYNC_16(smem_u32, gptr) \
    asm volatile("cp.async.cg.shared.global [%0], [%1], 16;" \
                 :: "r"(smem_u32), "l"(gptr) : "memory")
#define CP_ASYNC_COMMIT() asm volatile("cp.async.commit_group;" ::: "memory")
#define CP_ASYNC_WAIT0()  asm volatile("cp.async.wait_group 0;" ::: "memory")
#define CP_ASYNC_WAIT1()  asm volatile("cp.async.wait_group 1;" ::: "memory")
#define CP_ASYNC_WAIT2()  asm volatile("cp.async.wait_group 2;" ::: "memory")

#define LDSM_X4(r0, r1, r2, r3, addr) \
    asm volatile("ldmatrix.sync.aligned.m8n8.x4.shared.b16 {%0,%1,%2,%3}, [%4];" \
                 : "=r"(r0), "=r"(r1), "=r"(r2), "=r"(r3) : "r"(addr))
#define LDSM_X4_T(r0, r1, r2, r3, addr) \
    asm volatile("ldmatrix.sync.aligned.m8n8.x4.trans.shared.b16 {%0,%1,%2,%3}, [%4];" \
                 : "=r"(r0), "=r"(r1), "=r"(r2), "=r"(r3) : "r"(addr))

__device__ __forceinline__ void mma16816(float& c0, float& c1, float& c2, float& c3,
                                         uint32_t a0, uint32_t a1, uint32_t a2, uint32_t a3,
                                         uint32_t b0, uint32_t b1) {
    asm volatile(
        "mma.sync.aligned.m16n8k16.row.col.f32.bf16.bf16.f32 "
        "{%0,%1,%2,%3}, {%4,%5,%6,%7}, {%8,%9}, {%0,%1,%2,%3};"
        : "+f"(c0), "+f"(c1), "+f"(c2), "+f"(c3)
        : "r"(a0), "r"(a1), "r"(a2), "r"(a3), "r"(b0), "r"(b1));
}

__device__ __forceinline__ uint32_t pack_bf16x2(float lo, float hi) {
    uint32_t d;
    asm("cvt.rn.bf16x2.f32 %0, %1, %2;" : "=r"(d) : "f"(hi), "f"(lo));
    return d;
}

// ---------------------------------------------------------------------------
// Elementwise fp32 -> (bf16 hi, bf16 lo) split
// ---------------------------------------------------------------------------
__global__ void split_kernel(const float* __restrict__ in,
                             __nv_bfloat16* __restrict__ hi,
                             __nv_bfloat16* __restrict__ lo, int n4)
{
    const int i = blockIdx.x * blockDim.x + threadIdx.x;
    if (i >= n4) return;
    const float4 v = reinterpret_cast<const float4*>(in)[i];
    __nv_bfloat16 h0 = __float2bfloat16(v.x);
    __nv_bfloat16 h1 = __float2bfloat16(v.y);
    __nv_bfloat16 h2 = __float2bfloat16(v.z);
    __nv_bfloat16 h3 = __float2bfloat16(v.w);
    __nv_bfloat16 l0 = __float2bfloat16(v.x - __bfloat162float(h0));
    __nv_bfloat16 l1 = __float2bfloat16(v.y - __bfloat162float(h1));
    __nv_bfloat16 l2 = __float2bfloat16(v.z - __bfloat162float(h2));
    __nv_bfloat16 l3 = __float2bfloat16(v.w - __bfloat162float(h3));
    __nv_bfloat162* H = reinterpret_cast<__nv_bfloat162*>(hi);
    __nv_bfloat162* L = reinterpret_cast<__nv_bfloat162*>(lo);
    H[2*i]   = __nv_bfloat162(h0, h1);
    H[2*i+1] = __nv_bfloat162(h2, h3);
    L[2*i]   = __nv_bfloat162(l0, l1);
    L[2*i+1] = __nv_bfloat162(l2, l3);
}

// ---------------------------------------------------------------------------
// W [Kdim][Ndim] fp32 -> transposed split bf16 Th/Tl [Ndim][Kdim]
// ---------------------------------------------------------------------------
__global__ void transpose_split(const float* __restrict__ W,
                                __nv_bfloat16* __restrict__ Th,
                                __nv_bfloat16* __restrict__ Tl,
                                int Kdim, int Ndim)
{
    __shared__ float t[32][33];
    const int nb = blockIdx.x * 32;
    const int kb = blockIdx.y * 32;
    const int tx = threadIdx.x;
    const int ty = threadIdx.y;   // 0..7
    #pragma unroll
    for (int i = 0; i < 32; i += 8)
        t[ty + i][tx] = W[(size_t)(kb + ty + i) * Ndim + nb + tx];
    __syncthreads();
    #pragma unroll
    for (int i = 0; i < 32; i += 8) {
        const float v = t[tx][ty + i];
        const __nv_bfloat16 h = __float2bfloat16(v);
        const __nv_bfloat16 l = __float2bfloat16(v - __bfloat162float(h));
        const size_t o = (size_t)(nb + ty + i) * Kdim + kb + tx;
        Th[o] = h;
        Tl[o] = l;
    }
}

// ---------------------------------------------------------------------------
// HMMA split GEMM: C[M,N] = (Ah+Al)[M,1024] @ (Bh+Bl)^T (+bias)
//   CTA 128x128, BK=32, 8 warps @ 64x32, 4-stage cp.async, one sync/chunk.
//   EPI=0: fp32 C.  EPI=1: bf16 hi/lo C (Q third scaled 0.125).
// ---------------------------------------------------------------------------
static constexpr int GPITCH = 40;                       // bf16 per smem row
static constexpr uint32_t GTILE  = 128 * GPITCH * 2;    // 10240 B (one array)
static constexpr uint32_t GSTAGE = 2 * GTILE;           // A+B per stage
static constexpr int GEMM_SMEM = 4 * (int)GSTAGE;       // 81920 B

template <int EPI>
__global__ __launch_bounds__(256, 2)
void gemm_hmma_split(const __nv_bfloat16* __restrict__ Ah,
                     const __nv_bfloat16* __restrict__ Al,
                     const __nv_bfloat16* __restrict__ Bh,
                     const __nv_bfloat16* __restrict__ Bl,
                     const float* __restrict__ bias,
                     float* __restrict__ Cf,
                     __nv_bfloat16* __restrict__ Ch,
                     __nv_bfloat16* __restrict__ Cl,
                     int N)
{
    const uint32_t sb = smem_to_u32(dynsmem);
    const int tid  = threadIdx.x;
    const int wid  = tid >> 5;
    const int lane = tid & 31;
    const int wm   = wid & 1;
    const int wn   = wid >> 1;
    const int rowBase = blockIdx.y * 128;
    const int colBase = blockIdx.x * 128;
    constexpr int K = 1024;
    constexpr int NCHUNK = 96;

    const int ldRow = tid >> 1;
    const int ldCol = (tid & 1) * 16;
    const uint32_t ldOff = (uint32_t)(ldRow * GPITCH + ldCol) * 2;

    float acc[4][4][4];
    #pragma unroll
    for (int mt = 0; mt < 4; mt++)
        #pragma unroll
        for (int nt = 0; nt < 4; nt++)
            #pragma unroll
            for (int q = 0; q < 4; q++) acc[mt][nt][q] = 0.0f;

    auto issue_loads = [&](int c) {
        const int st = c & 3;
        const int p  = c >> 5;
        const int ks = (c & 31) * 32;
        const __nv_bfloat16* Ap = (p == 1) ? Al : Ah;
        const __nv_bfloat16* Bp = (p == 2) ? Bl : Bh;
        const __nv_bfloat16* ga = Ap + (size_t)(rowBase + ldRow) * K + ks + ldCol;
        const __nv_bfloat16* gb = Bp + (size_t)(colBase + ldRow) * K + ks + ldCol;
        const uint32_t sa = sb + st * GSTAGE + ldOff;
        const uint32_t sB = sa + GTILE;
        CP_ASYNC_16(sa,      ga);
        CP_ASYNC_16(sa + 16, ga + 8);
        CP_ASYNC_16(sB,      gb);
        CP_ASYNC_16(sB + 16, gb + 8);
        CP_ASYNC_COMMIT();
    };

    issue_loads(0);
    issue_loads(1);
    issue_loads(2);

    // per-warp fragment smem offsets (bytes)
    const int fr  = lane & 15;
    const int fc  = (lane >> 4) * 8;
    const uint32_t aFrag = (uint32_t)((wm * 64 + fr) * GPITCH + fc) * 2;
    const uint32_t bFrag = (uint32_t)((wn * 32 + fr) * GPITCH + fc) * 2 + GTILE;

    for (int c = 0; c < NCHUNK; c++) {
        if (c <= NCHUNK - 3)      { CP_ASYNC_WAIT2(); }
        else if (c == NCHUNK - 2) { CP_ASYNC_WAIT1(); }
        else                      { CP_ASYNC_WAIT0(); }
        __syncthreads();
        if (c + 3 < NCHUNK) issue_loads(c + 3);

        const uint32_t stB = sb + (uint32_t)(c & 3) * GSTAGE;

        #pragma unroll
        for (int kk = 0; kk < 32; kk += 16) {
            uint32_t af[4][4];
            #pragma unroll
            for (int mt = 0; mt < 4; mt++)
                LDSM_X4(af[mt][0], af[mt][1], af[mt][2], af[mt][3],
                        stB + aFrag + (uint32_t)(mt * 16 * GPITCH + kk) * 2);
            uint32_t bf[4][2];
            #pragma unroll
            for (int np = 0; np < 2; np++) {
                uint32_t b0, b1, b2, b3;
                LDSM_X4(b0, b1, b2, b3,
                        stB + bFrag + (uint32_t)(np * 16 * GPITCH + kk) * 2);
                bf[np*2][0] = b0; bf[np*2+1][0] = b1;
                bf[np*2][1] = b2; bf[np*2+1][1] = b3;
            }
            #pragma unroll
            for (int mt = 0; mt < 4; mt++)
                #pragma unroll
                for (int nt = 0; nt < 4; nt++)
                    mma16816(acc[mt][nt][0], acc[mt][nt][1],
                             acc[mt][nt][2], acc[mt][nt][3],
                             af[mt][0], af[mt][1], af[mt][2], af[mt][3],
                             bf[nt][0], bf[nt][1]);
        }
    }

    // Epilogue
    #pragma unroll
    for (int mt = 0; mt < 4; mt++) {
        const int r0 = rowBase + wm * 64 + mt * 16 + (lane >> 2);
        #pragma unroll
        for (int nt = 0; nt < 4; nt++) {
            const int col = colBase + wn * 32 + nt * 8 + (lane & 3) * 2;
            const float b0 = bias[col], b1 = bias[col + 1];
            float v0 = acc[mt][nt][0] + b0, v1 = acc[mt][nt][1] + b1;
            float v2 = acc[mt][nt][2] + b0, v3 = acc[mt][nt][3] + b1;
            if (EPI == 1) {
                const float sc = (col >= 1024 && col < 2048) ? 0.125f : 1.0f;
                v0 *= sc; v1 *= sc; v2 *= sc; v3 *= sc;
                const __nv_bfloat16 h0 = __float2bfloat16(v0);
                const __nv_bfloat16 h1 = __float2bfloat16(v1);
                const __nv_bfloat16 h2 = __float2bfloat16(v2);
                const __nv_bfloat16 h3 = __float2bfloat16(v3);
                *reinterpret_cast<__nv_bfloat162*>(&Ch[(size_t)r0 * N + col]) =
                    __nv_bfloat162(h0, h1);
                *reinterpret_cast<__nv_bfloat162*>(&Ch[(size_t)(r0 + 8) * N + col]) =
                    __nv_bfloat162(h2, h3);
                *reinterpret_cast<__nv_bfloat162*>(&Cl[(size_t)r0 * N + col]) =
                    __nv_bfloat162(__float2bfloat16(v0 - __bfloat162float(h0)),
                                   __float2bfloat16(v1 - __bfloat162float(h1)));
                *reinterpret_cast<__nv_bfloat162*>(&Cl[(size_t)(r0 + 8) * N + col]) =
                    __nv_bfloat162(__float2bfloat16(v2 - __bfloat162float(h2)),
                                   __float2bfloat16(v3 - __bfloat162float(h3)));
            } else {
                *reinterpret_cast<float2*>(&Cf[(size_t)r0 * N + col]) =
                    make_float2(v0, v1);
                *reinterpret_cast<float2*>(&Cf[(size_t)(r0 + 8) * N + col]) =
                    make_float2(v2, v3);
            }
        }
    }
}

// ---------------------------------------------------------------------------
// HMMA flash attention, double-buffered K/V stages.
// CTA = (qtile 128 rows, b, h); 8 warps x 16 q-rows.
// ---------------------------------------------------------------------------
static constexpr int APITCH = 72;                        // bf16 pitch
static constexpr int ATILE  = 128 * APITCH * 2;          // 18432 B
static constexpr int ASTAGE = 4 * ATILE;                 // K/V hi/lo per stage
static constexpr int AT_SMEM = 2 * ASTAGE;               // 147456 B

__global__ __launch_bounds__(256, 1)
void flash_attn_hmma(const __nv_bfloat16* __restrict__ QKVh,
                     const __nv_bfloat16* __restrict__ QKVl,
                     __nv_bfloat16* __restrict__ Oh,
                     __nv_bfloat16* __restrict__ Ol)
{
    const uint32_t sb = smem_to_u32(dynsmem);

    const int tid  = threadIdx.x;
    const int w    = tid >> 5;
    const int lane = tid & 31;
    const int qt = blockIdx.x;
    const int bh = blockIdx.y;
    const int b = bh >> 4, h = bh & 15;
    const size_t baseRow = (size_t)b * N_;
    const int hcol = h * HD;

    const int ldr = tid >> 1;
    const int ldc = (tid & 1) * 32;
    const uint32_t ldOffBase = (uint32_t)(ldr * APITCH + ldc) * 2;

    auto issue_kv = [&](int kt) {
        const uint32_t st = sb + (uint32_t)(kt & 1) * ASTAGE;
        const size_t grow = (baseRow + kt * 128 + ldr) * QKV + hcol + ldc;
        #pragma unroll
        for (int s = 0; s < 4; s++) {
            const uint32_t so = ldOffBase + s * 16;
            const size_t go = grow + s * 8;
            CP_ASYNC_16(st + so,             QKVh + go);          // K hi
            CP_ASYNC_16(st + ATILE + so,     QKVl + go);          // K lo
            CP_ASYNC_16(st + 2 * ATILE + so, QKVh + go + 2048);   // V hi
            CP_ASYNC_16(st + 3 * ATILE + so, QKVl + go + 2048);   // V lo
        }
        CP_ASYNC_COMMIT();
    };

    // ---- stage Q tile through stage-0 K area ----
    {
        const size_t grow = (baseRow + qt * 128 + ldr) * QKV + 1024 + hcol + ldc;
        #pragma unroll
        for (int s = 0; s < 4; s++) {
            const uint32_t so = ldOffBase + s * 16;
            CP_ASYNC_16(sb + so,         QKVh + grow + s * 8);
            CP_ASYNC_16(sb + ATILE + so, QKVl + grow + s * 8);
        }
        CP_ASYNC_COMMIT();
        CP_ASYNC_WAIT0();
    }
    __syncthreads();

    uint32_t qh[4][4], ql[4][4];
    {
        const int row = w * 16 + (lane & 15);
        #pragma unroll
        for (int kc = 0; kc < 4; kc++) {
            const int col = kc * 16 + (lane >> 4) * 8;
            LDSM_X4(qh[kc][0], qh[kc][1], qh[kc][2], qh[kc][3],
                    sb + (uint32_t)(row * APITCH + col) * 2);
            LDSM_X4(ql[kc][0], ql[kc][1], ql[kc][2], ql[kc][3],
                    sb + ATILE + (uint32_t)(row * APITCH + col) * 2);
        }
    }
    __syncthreads();
    issue_kv(0);

    float o[8][4];
    #pragma unroll
    for (int nt = 0; nt < 8; nt++)
        #pragma unroll
        for (int q = 0; q < 4; q++) o[nt][q] = 0.0f;
    float m0 = -1e30f, m1 = -1e30f, l0 = 0.0f, l1 = 0.0f;

    const int fr  = lane & 15;
    const int fc8 = (lane >> 4) * 8;

    for (int kt = 0; kt < 8; kt++) {
        if (kt + 1 < 8) { issue_kv(kt + 1); CP_ASYNC_WAIT1(); }
        else            { CP_ASYNC_WAIT0(); }
        __syncthreads();

        const uint32_t sKh = sb + (uint32_t)(kt & 1) * ASTAGE;
        const uint32_t sKl = sKh + ATILE;
        const uint32_t sVh = sKh + 2 * ATILE;
        const uint32_t sVl = sKh + 3 * ATILE;

        // ---- S = Q K^T, 3 bf16 passes ----
        float s[16][4];
        #pragma unroll
        for (int nt = 0; nt < 16; nt++)
            #pragma unroll
            for (int q = 0; q < 4; q++) s[nt][q] = 0.0f;

        #pragma unroll
        for (int kc = 0; kc < 4; kc++) {
            const int col = kc * 16 + fc8;
            #pragma unroll
            for (int np = 0; np < 8; np++) {
                uint32_t b0, b1, b2, b3;
                LDSM_X4(b0, b1, b2, b3,
                        sKh + (uint32_t)((np * 16 + fr) * APITCH + col) * 2);
                mma16816(s[2*np][0], s[2*np][1], s[2*np][2], s[2*np][3],
                         qh[kc][0], qh[kc][1], qh[kc][2], qh[kc][3], b0, b2);
                mma16816(s[2*np+1][0], s[2*np+1][1], s[2*np+1][2], s[2*np+1][3],
                         qh[kc][0], qh[kc][1], qh[kc][2], qh[kc][3], b1, b3);
                mma16816(s[2*np][0], s[2*np][1], s[2*np][2], s[2*np][3],
                         ql[kc][0], ql[kc][1], ql[kc][2], ql[kc][3], b0, b2);
                mma16816(s[2*np+1][0], s[2*np+1][1], s[2*np+1][2], s[2*np+1][3],
                         ql[kc][0], ql[kc][1], ql[kc][2], ql[kc][3], b1, b3);
                LDSM_X4(b0, b1, b2, b3,
                        sKl + (uint32_t)((np * 16 + fr) * APITCH + col) * 2);
                mma16816(s[2*np][0], s[2*np][1], s[2*np][2], s[2*np][3],
                         qh[kc][0], qh[kc][1], qh[kc][2], qh[kc][3], b0, b2);
                mma16816(s[2*np+1][0], s[2*np+1][1], s[2*np+1][2], s[2*np+1][3],
                         qh[kc][0], qh[kc][1], qh[kc][2], qh[kc][3], b1, b3);
            }
        }

        // ---- online softmax ----
        float tm0 = -1e30f, tm1 = -1e30f;
        #pragma unroll
        for (int nt = 0; nt < 16; nt++) {
            tm0 = fmaxf(tm0, fmaxf(s[nt][0], s[nt][1]));
            tm1 = fmaxf(tm1, fmaxf(s[nt][2], s[nt][3]));
        }
        tm0 = fmaxf(tm0, __shfl_xor_sync(0xffffffffu, tm0, 1));
        tm0 = fmaxf(tm0, __shfl_xor_sync(0xffffffffu, tm0, 2));
        tm1 = fmaxf(tm1, __shfl_xor_sync(0xffffffffu, tm1, 1));
        tm1 = fmaxf(tm1, __shfl_xor_sync(0xffffffffu, tm1, 2));
        const float mn0 = fmaxf(m0, tm0), mn1 = fmaxf(m1, tm1);
        const float cr0 = __expf(m0 - mn0), cr1 = __expf(m1 - mn1);
        m0 = mn0; m1 = mn1;
        float ts0 = 0.0f, ts1 = 0.0f;
        #pragma unroll
        for (int nt = 0; nt < 16; nt++) {
            s[nt][0] = __expf(s[nt][0] - mn0);
            s[nt][1] = __expf(s[nt][1] - mn0);
            s[nt][2] = __expf(s[nt][2] - mn1);
            s[nt][3] = __expf(s[nt][3] - mn1);
            ts0 += s[nt][0] + s[nt][1];
            ts1 += s[nt][2] + s[nt][3];
        }
        ts0 += __shfl_xor_sync(0xffffffffu, ts0, 1);
        ts0 += __shfl_xor_sync(0xffffffffu, ts0, 2);
        ts1 += __shfl_xor_sync(0xffffffffu, ts1, 1);
        ts1 += __shfl_xor_sync(0xffffffffu, ts1, 2);
        l0 = l0 * cr0 + ts0;
        l1 = l1 * cr1 + ts1;
        #pragma unroll
        for (int nt = 0; nt < 8; nt++) {
            o[nt][0] *= cr0; o[nt][1] *= cr0;
            o[nt][2] *= cr1; o[nt][3] *= cr1;
        }

        // ---- O += P V, 3 passes ----
        #pragma unroll
        for (int kc = 0; kc < 8; kc++) {
            uint32_t pa_h[4], pa_l[4];
            #pragma unroll
            for (int half = 0; half < 2; half++) {
                const int nt = 2 * kc + half;
                const __nv_bfloat16 ha = __float2bfloat16(s[nt][0]);
                const __nv_bfloat16 hb = __float2bfloat16(s[nt][1]);
                const __nv_bfloat16 hc = __float2bfloat16(s[nt][2]);
                const __nv_bfloat16 hd_ = __float2bfloat16(s[nt][3]);
                __nv_bfloat162 t0(ha, hb), t1(hc, hd_);
                pa_h[half * 2]     = *reinterpret_cast<uint32_t*>(&t0);
                pa_h[half * 2 + 1] = *reinterpret_cast<uint32_t*>(&t1);
                pa_l[half * 2] = pack_bf16x2(s[nt][0] - __bfloat162float(ha),
                                             s[nt][1] - __bfloat162float(hb));
                pa_l[half * 2 + 1] = pack_bf16x2(s[nt][2] - __bfloat162float(hc),
                                                 s[nt][3] - __bfloat162float(hd_));
            }
            const int vrow = kc * 16 + fr;
            #pragma unroll
            for (int np = 0; np < 4; np++) {
                const int vcol = np * 16 + fc8;
                uint32_t b0, b1, b2, b3;
                LDSM_X4_T(b0, b1, b2, b3,
                          sVh + (uint32_t)(vrow * APITCH + vcol) * 2);
                mma16816(o[2*np][0], o[2*np][1], o[2*np][2], o[2*np][3],
                         pa_h[0], pa_h[1], pa_h[2], pa_h[3], b0, b1);
                mma16816(o[2*np+1][0], o[2*np+1][1], o[2*np+1][2], o[2*np+1][3],
                         pa_h[0], pa_h[1], pa_h[2], pa_h[3], b2, b3);
                mma16816(o[2*np][0], o[2*np][1], o[2*np][2], o[2*np][3],
                         pa_l[0], pa_l[1], pa_l[2], pa_l[3], b0, b1);
                mma16816(o[2*np+1][0], o[2*np+1][1], o[2*np+1][2], o[2*np+1][3],
                         pa_l[0], pa_l[1], pa_l[2], pa_l[3], b2, b3);
                LDSM_X4_T(b0, b1, b2, b3,
                          sVl + (uint32_t)(vrow * APITCH + vcol) * 2);
                mma16816(o[2*np][0], o[2*np][1], o[2*np][2], o[2*np][3],
                         pa_h[0], pa_h[1], pa_h[2], pa_h[3], b0, b1);
                mma16816(o[2*np+1][0], o[2*np+1][1], o[2*np+1][2], o[2*np+1][3],
                         pa_h[0], pa_h[1], pa_h[2], pa_h[3], b2, b3);
            }
        }
        __syncthreads();   // all warps done reading this stage before reuse
    }

    // ---- epilogue ----
    const float inv0 = 1.0f / l0, inv1 = 1.0f / l1;
    const size_t r0 = baseRow + qt * 128 + w * 16 + (lane >> 2);
    #pragma unroll
    for (int nt = 0; nt < 8; nt++) {
        const int col = hcol + nt * 8 + (lane & 3) * 2;
        const float v0 = o[nt][0] * inv0, v1 = o[nt][1] * inv0;
        const float v2 = o[nt][2] * inv1, v3 = o[nt][3] * inv1;
        const __nv_bfloat16 h0 = __float2bfloat16(v0);
        const __nv_bfloat16 h1 = __float2bfloat16(v1);
        const __nv_bfloat16 h2 = __float2bfloat16(v2);
        const __nv_bfloat16 h3 = __float2bfloat16(v3);
        *reinterpret_cast<__nv_bfloat162*>(&Oh[r0 * EMB + col]) = __nv_bfloat162(h0, h1);
        *reinterpret_cast<__nv_bfloat162*>(&Oh[(r0 + 8) * EMB + col]) = __nv_bfloat162(h2, h3);
        *reinterpret_cast<__nv_bfloat162*>(&Ol[r0 * EMB + col]) =
            __nv_bfloat162(__float2bfloat16(v0 - __bfloat162float(h0)),
                           __float2bfloat16(v1 - __bfloat162float(h1)));
        *reinterpret_cast<__nv_bfloat162*>(&Ol[(r0 + 8) * EMB + col]) =
            __nv_bfloat162(__float2bfloat16(v2 - __bfloat162float(h2)),
                           __float2bfloat16(v3 - __bfloat162float(h3)));
    }
}

// ---------------------------------------------------------------------------
extern "C" void kernel_launch(void* const* d_in, const int* in_sizes, int n_in,
                              void* d_out, int out_size)
{
    const float* x     = (const float*)d_in[0];
    const float* W_qkv = (const float*)d_in[1];
    const float* b_qkv = (const float*)d_in[2];
    const float* W_out = (const float*)d_in[3];
    const float* b_out = (const float*)d_in[4];
    float* out = (float*)d_out;

    __nv_bfloat16 *xh, *xl, *wqh, *wql, *woh, *wol, *qkh, *qkl, *ath, *atl;
    cudaGetSymbolAddress((void**)&xh,  g_xh);
    cudaGetSymbolAddress((void**)&xl,  g_xl);
    cudaGetSymbolAddress((void**)&wqh, g_WqTh);
    cudaGetSymbolAddress((void**)&wql, g_WqTl);
    cudaGetSymbolAddress((void**)&woh, g_WoTh);
    cudaGetSymbolAddress((void**)&wol, g_WoTl);
    cudaGetSymbolAddress((void**)&qkh, g_qkh);
    cudaGetSymbolAddress((void**)&qkl, g_qkl);
    cudaGetSymbolAddress((void**)&ath, g_ath);
    cudaGetSymbolAddress((void**)&atl, g_atl);

    cudaFuncSetAttribute(flash_attn_hmma,
                         cudaFuncAttributeMaxDynamicSharedMemorySize, AT_SMEM);
    cudaFuncSetAttribute(gemm_hmma_split<1>,
                         cudaFuncAttributeMaxDynamicSharedMemorySize, GEMM_SMEM);
    cudaFuncSetAttribute(gemm_hmma_split<0>,
                         cudaFuncAttributeMaxDynamicSharedMemorySize, GEMM_SMEM);

    // 0) operand conversions
    split_kernel<<<(M_ * EMB / 4 + 255) / 256, 256>>>(x, xh, xl, M_ * EMB / 4);
    transpose_split<<<dim3(QKV / 32, EMB / 32), dim3(32, 8)>>>(W_qkv, wqh, wql, EMB, QKV);
    transpose_split<<<dim3(EMB / 32, EMB / 32), dim3(32, 8)>>>(W_out, woh, wol, EMB, EMB);

    // 1) QKV projection -> bf16 hi/lo qkv (Q third pre-scaled by 0.125)
    gemm_hmma_split<1><<<dim3(QKV / 128, M_ / 128), 256, GEMM_SMEM>>>(
        xh, xl, wqh, wql, b_qkv, nullptr, qkh, qkl, QKV);

    // 2) attention (tensorized, double-buffered)
    flash_attn_hmma<<<dim3(8, B_ * H_), 256, AT_SMEM>>>(qkh, qkl, ath, atl);

    // 3) output projection -> fp32 out
    gemm_hmma_split<0><<<dim3(EMB / 128, M_ / 128), 256, GEMM_SMEM>>>(
        ath, atl, woh, wol, b_out, out, nullptr, nullptr, EMB);
}